// round 16
// baseline (speedup 1.0000x reference)
#include <cuda_runtime.h>
#include <cuda_fp16.h>
#include <cstdint>

#define N_TOK 4096
#define INCH  256
#define HEADS 8
#define DHEAD 64
#define PROJ  512

// Scratch (allocation-free rule: __device__ globals)
__device__ __half g_xh[N_TOK][INCH];             // X fp16 (2 MB)
__device__ __half g_wh[3][PROJ][INCH];           // Wq/Wk/Wv fp16 (0.75 MB)
__device__ __half g_qh[HEADS][N_TOK][DHEAD];     // Q fp16 (4 MB)
__device__ __half g_kh[HEADS][N_TOK][DHEAD];     // K fp16 (4 MB)
__device__ __half g_vh[HEADS][N_TOK][DHEAD];     // V fp16 (4 MB)
__device__ float  g_parts[HEADS][N_TOK][DHEAD];  // per-head normalized O (8 MB)

__device__ __forceinline__ float fast_sigmoid(float x) {
    float t;
    asm("tanh.approx.f32 %0, %1;" : "=f"(t) : "f"(x * 0.5f));
    return fmaf(t, 0.5f, 0.5f);
}

__device__ __forceinline__ uint32_t pack_f16(float lo, float hi) {
    uint32_t r;
    asm("cvt.rn.f16x2.f32 %0, %1, %2;" : "=r"(r) : "f"(hi), "f"(lo));
    return r;
}

__device__ __forceinline__ void mma_f16(float c[4], const uint32_t a[4], uint32_t b0, uint32_t b1) {
    asm volatile(
        "mma.sync.aligned.m16n8k16.row.col.f32.f16.f16.f32 "
        "{%0,%1,%2,%3}, {%4,%5,%6,%7}, {%8,%9}, {%0,%1,%2,%3};"
        : "+f"(c[0]), "+f"(c[1]), "+f"(c[2]), "+f"(c[3])
        : "r"(a[0]), "r"(a[1]), "r"(a[2]), "r"(a[3]), "r"(b0), "r"(b1));
}

__device__ __forceinline__ uint32_t smem_u32(const void* p) {
    uint32_t a;
    asm("{ .reg .u64 t; cvta.to.shared.u64 t, %1; cvt.u32.u64 %0, t; }" : "=r"(a) : "l"(p));
    return a;
}

__device__ __forceinline__ void cpasync16(uint32_t dst, const void* src) {
    asm volatile("cp.async.cg.shared.global [%0], [%1], 16;" :: "r"(dst), "l"(src) : "memory");
}

// ---------------------------------------------------------------------------
// Convert: X, Wq, Wk, Wv f32 -> fp16 scratch. 360448 float4 total.
// ---------------------------------------------------------------------------
__global__ void convert_kernel(const float* __restrict__ X,
                               const float* __restrict__ Wq,
                               const float* __restrict__ Wk,
                               const float* __restrict__ Wv) {
    int i = blockIdx.x * blockDim.x + threadIdx.x;   // float4 index
    const float* src;
    __half* dst;
    int off;
    if (i < 262144) {                // X: 4096*256/4
        src = X; dst = &g_xh[0][0]; off = i;
    } else {
        int j = i - 262144;          // W: 3 * 32768
        int w = j >> 15; off = j & 32767;
        src = (w == 0) ? Wq : (w == 1) ? Wk : Wv;
        dst = &g_wh[w][0][0];
    }
    float4 v = ((const float4*)src)[off];
    uint2 o;
    o.x = pack_f16(v.x, v.y);
    o.y = pack_f16(v.z, v.w);
    ((uint2*)dst)[off] = o;
}

// ---------------------------------------------------------------------------
// Projection v4: fused fp16 GEMM C[4096][1536] = Xh @ Wh^T + b -> Q/K/V fp16.
// CTA 128(m) x 128(p), 512 threads, warps 4(m) x 4(p), K-chunks of 64,
// cp.async double buffer. Grid (32, 12) — halves L2 traffic vs 64x64 tiles
// (X read by 12 p-strips instead of 24; W by 32 m-strips instead of 64).
// ---------------------------------------------------------------------------
#define PJ_STG 18432u            // 128 rows * 72 half * 2B per operand stage
#define PROJ_SMEM (4 * PJ_STG)   // 73728 B

__global__ __launch_bounds__(512, 1) void proj_kernel(
        const float* __restrict__ bq, const float* __restrict__ bk,
        const float* __restrict__ bv) {
    extern __shared__ char smem[];
    const uint32_t sbase = smem_u32(smem);
    const uint32_t sX = sbase;                 // X stages at 0, PJ_STG
    const uint32_t sW = sbase + 2 * PJ_STG;    // W stages follow

    const int m0  = blockIdx.x * 128;
    const int p0g = blockIdx.y * 128;          // global p in [0,1536)
    const int which = blockIdx.y >> 2;         // 4 blocks of 128 per projection
    const int p0i = p0g & 511;                 // p within this projection
    const float* bias = (which == 0) ? bq : (which == 1) ? bk : bv;
    __half* dst = (which == 0) ? &g_qh[0][0][0] : (which == 1) ? &g_kh[0][0][0]
                                                               : &g_vh[0][0][0];

    const int tid = threadIdx.x;
    const int lane = tid & 31, warp = tid >> 5;
    const int wm = warp & 3, wn = warp >> 2;   // 4(m) x 4(p)
    const int g = lane >> 2, tg = lane & 3;

    const int a_row = lane & 15;
    const int a_col = (lane >> 4) * 8;
    const int kb_row = (lane & 7) + ((lane >> 4) & 1) * 8;
    const int kb_col = ((lane >> 3) & 1) * 8;

    const __half* Xg = &g_xh[m0][0];
    const __half* Wg = &g_wh[which][p0i][0];

    float acc[2][4][4] = {};   // [m-chunk][p-block n8][frag]

    // prefetch chunk 0: 128 rows x 8 col-chunks per operand = 1024; 512 thr x 2
    {
        #pragma unroll
        for (int j = 0; j < 2; j++) {
            int e = tid + j * 512;
            int l = e >> 3, c = e & 7;
            cpasync16(sX + (uint32_t)(l * 144 + c * 16), Xg + l * INCH + c * 8);
            cpasync16(sW + (uint32_t)(l * 144 + c * 16), Wg + l * INCH + c * 8);
        }
        asm volatile("cp.async.commit_group;" ::: "memory");
    }

    #pragma unroll
    for (int kc = 0; kc < INCH / 64; kc++) {
        const int stg = kc & 1;
        asm volatile("cp.async.wait_group 0;" ::: "memory");
        __syncthreads();

        if (kc + 1 < INCH / 64) {
            const int k0n = (kc + 1) * 64;
            const uint32_t xd = sX + (uint32_t)(1 - stg) * PJ_STG;
            const uint32_t wd = sW + (uint32_t)(1 - stg) * PJ_STG;
            #pragma unroll
            for (int j = 0; j < 2; j++) {
                int e = tid + j * 512;
                int l = e >> 3, c = e & 7;
                cpasync16(xd + (uint32_t)(l * 144 + c * 16), Xg + l * INCH + k0n + c * 8);
                cpasync16(wd + (uint32_t)(l * 144 + c * 16), Wg + l * INCH + k0n + c * 8);
            }
            asm volatile("cp.async.commit_group;" ::: "memory");
        }

        const uint32_t xb = sX + (uint32_t)stg * PJ_STG;
        const uint32_t wb = sW + (uint32_t)stg * PJ_STG;

        #pragma unroll
        for (int ks = 0; ks < 4; ks++) {
            uint32_t am[2][4];
            #pragma unroll
            for (int mc = 0; mc < 2; mc++) {
                uint32_t addr = xb + (uint32_t)((wm * 32 + mc * 16 + a_row) * 144
                                                + (ks * 16 + a_col) * 2);
                asm volatile(
                    "ldmatrix.sync.aligned.m8n8.x4.shared.b16 {%0,%1,%2,%3}, [%4];"
                    : "=r"(am[mc][0]), "=r"(am[mc][1]), "=r"(am[mc][2]), "=r"(am[mc][3])
                    : "r"(addr));
            }
            #pragma unroll
            for (int gi = 0; gi < 2; gi++) {
                uint32_t addr = wb + (uint32_t)((wn * 32 + gi * 16 + kb_row) * 144
                                                + (ks * 16 + kb_col) * 2);
                uint32_t b0_, b1_, b2_, b3_;
                asm volatile(
                    "ldmatrix.sync.aligned.m8n8.x4.shared.b16 {%0,%1,%2,%3}, [%4];"
                    : "=r"(b0_), "=r"(b1_), "=r"(b2_), "=r"(b3_) : "r"(addr));
                #pragma unroll
                for (int mc = 0; mc < 2; mc++) {
                    mma_f16(acc[mc][gi*2],     am[mc], b0_, b1_);
                    mma_f16(acc[mc][gi*2 + 1], am[mc], b2_, b3_);
                }
            }
        }
    }

    // epilogue: add bias, fp16, store pairs
    #pragma unroll
    for (int mc = 0; mc < 2; mc++) {
        int row0 = m0 + wm * 32 + mc * 16 + g;
        #pragma unroll
        for (int j = 0; j < 4; j++) {
            int inner = p0i + wn * 32 + (j >> 1) * 16 + (j & 1) * 8 + 2 * tg;  // [0,512)
            float b0 = bias[inner], b1 = bias[inner + 1];
            int hd = inner >> 6, d = inner & 63;
            *(uint32_t*)&dst[(hd * N_TOK + row0    ) * DHEAD + d] =
                pack_f16(acc[mc][j][0] + b0, acc[mc][j][1] + b1);
            *(uint32_t*)&dst[(hd * N_TOK + row0 + 8) * DHEAD + d] =
                pack_f16(acc[mc][j][2] + b0, acc[mc][j][3] + b1);
        }
    }
}

// ---------------------------------------------------------------------------
// Attention v4 (proven): one (query-tile 128, head) per CTA; grid (32, 8),
// 512 threads, warps 8(m) x 2(n). K via ldmatrix, V via ldmatrix.trans,
// sigmoid+pack in regs, cp.async double buffer. 1 CTA/SM.
// Epilogue: in-CTA wn reduction + Z normalization in reused smem.
// ---------------------------------------------------------------------------
#define KV_STG 9216u   // 64 rows * 72 f16 * 2B (144B rows: LDSM conflict-free)
#define ATTN_SMEM (4 * KV_STG)

__global__ __launch_bounds__(512, 1) void attn_kernel() {
    extern __shared__ char smem[];
    const uint32_t sbase = smem_u32(smem);
    const uint32_t sK = sbase;                 // K stages at 0, KV_STG
    const uint32_t sV = sbase + 2 * KV_STG;    // V stages follow

    const int m0 = blockIdx.x * 128;
    const int h  = blockIdx.y;
    const int tid = threadIdx.x;
    const int lane = tid & 31, warp = tid >> 5;
    const int wm = warp & 7, wn = warp >> 3;   // 8(m) x 2(n)
    const int g = lane >> 2, tg = lane & 3;
    const int r0 = wm * 16 + g;                // [0, 128)

    // Q fragments fp16: qa[kstep][0..3] for m16n8k16
    uint32_t qa[4][4];
    {
        const __half* Qg = &g_qh[h][m0][0];
        #pragma unroll
        for (int ks = 0; ks < 4; ks++) {
            qa[ks][0] = *(const uint32_t*)&Qg[ r0      * DHEAD + ks*16 + 2*tg    ];
            qa[ks][1] = *(const uint32_t*)&Qg[(r0 + 8) * DHEAD + ks*16 + 2*tg    ];
            qa[ks][2] = *(const uint32_t*)&Qg[ r0      * DHEAD + ks*16 + 2*tg + 8];
            qa[ks][3] = *(const uint32_t*)&Qg[(r0 + 8) * DHEAD + ks*16 + 2*tg + 8];
        }
    }

    const __half* Kg = &g_kh[h][0][0];
    const __half* Vg = &g_vh[h][0][0];

    // ldmatrix lane roles
    const int lm_row = (lane & 7) + ((lane >> 3) & 1) * 8;   // V: k row within 16
    const int lm_col = ((lane >> 4) & 1) * 8;                // V: n col within 16
    const int kb_row = (lane & 7) + ((lane >> 4) & 1) * 8;   // K: n row within 16
    const int kb_col = ((lane >> 3) & 1) * 8;                // K: k half

    float oacc[8][4] = {};
    float zacc[2] = {};

    // prefetch tile 0: 512 threads cover 64 rows x 8 chunks of K and V
    {
        int l = tid >> 3, c = tid & 7;
        cpasync16(sK + (uint32_t)(l * 144 + c * 16), Kg + l * 64 + c * 8);
        cpasync16(sV + (uint32_t)(l * 144 + c * 16), Vg + l * 64 + c * 8);
        asm volatile("cp.async.commit_group;" ::: "memory");
    }

    for (int t = 0; t < N_TOK / 64; ++t) {
        const int stg = t & 1;
        asm volatile("cp.async.wait_group 0;" ::: "memory");
        __syncthreads();

        // prefetch t+1 into other stage
        if (t + 1 < N_TOK / 64) {
            const __half* Kn = Kg + (t + 1) * 64 * DHEAD;
            const __half* Vn = Vg + (t + 1) * 64 * DHEAD;
            const uint32_t kd = sK + (uint32_t)(1 - stg) * KV_STG;
            const uint32_t vd = sV + (uint32_t)(1 - stg) * KV_STG;
            int l = tid >> 3, c = tid & 7;
            cpasync16(kd + (uint32_t)(l * 144 + c * 16), Kn + l * 64 + c * 8);
            cpasync16(vd + (uint32_t)(l * 144 + c * 16), Vn + l * 64 + c * 8);
            asm volatile("cp.async.commit_group;" ::: "memory");
        }

        const uint32_t kb = sK + (uint32_t)stg * KV_STG;
        const uint32_t vb = sV + (uint32_t)stg * KV_STG;

        // ---- S = Q @ K^T (fp16 MMA), warp cols [wn*32, +32)
        float sacc[4][4] = {};
        #pragma unroll
        for (int ks = 0; ks < 4; ks++) {
            #pragma unroll
            for (int gi = 0; gi < 2; gi++) {
                uint32_t addr = kb
                    + (uint32_t)((wn * 32 + gi * 16 + kb_row) * 144)
                    + (uint32_t)((ks * 16 + kb_col) * 2);
                uint32_t b0_, b1_, b2_, b3_;
                asm volatile(
                    "ldmatrix.sync.aligned.m8n8.x4.shared.b16 {%0,%1,%2,%3}, [%4];"
                    : "=r"(b0_), "=r"(b1_), "=r"(b2_), "=r"(b3_) : "r"(addr));
                mma_f16(sacc[gi*2],     qa[ks], b0_, b1_);
                mma_f16(sacc[gi*2 + 1], qa[ks], b2_, b3_);
            }
        }

        // ---- sigmoid -> P (fp16 A-fragments in regs), Z accumulation
        uint32_t pf[2][4];
        #pragma unroll
        for (int j = 0; j < 4; j++) {
            float p0 = fast_sigmoid(sacc[j][0]);
            float p1 = fast_sigmoid(sacc[j][1]);
            float p2 = fast_sigmoid(sacc[j][2]);
            float p3 = fast_sigmoid(sacc[j][3]);
            zacc[0] += p0 + p1;
            zacc[1] += p2 + p3;
            pf[j >> 1][(j & 1) * 2 + 0] = pack_f16(p0, p1);
            pf[j >> 1][(j & 1) * 2 + 1] = pack_f16(p2, p3);
        }

        // ---- O += P @ V (fp16 MMA), warp's l-slice = [wn*32 + kc*16, +16)
        #pragma unroll
        for (int kc = 0; kc < 2; kc++) {
            const uint32_t rowb = vb + (uint32_t)((wn * 32 + kc * 16 + lm_row) * 144);
            #pragma unroll
            for (int jp = 0; jp < 4; jp++) {
                uint32_t r0_, r1_, r2_, r3_;
                uint32_t addr = rowb + (uint32_t)((jp * 16 + lm_col) * 2);
                asm volatile(
                    "ldmatrix.sync.aligned.m8n8.x4.trans.shared.b16 {%0,%1,%2,%3}, [%4];"
                    : "=r"(r0_), "=r"(r1_), "=r"(r2_), "=r"(r3_) : "r"(addr));
                mma_f16(oacc[2*jp],     pf[kc], r0_, r1_);
                mma_f16(oacc[2*jp + 1], pf[kc], r2_, r3_);
            }
        }
    }

    // ================= epilogue: in-CTA reduction + normalize =================
    float z0 = zacc[0], z1 = zacc[1];
    z0 += __shfl_xor_sync(0xffffffff, z0, 1);
    z0 += __shfl_xor_sync(0xffffffff, z0, 2);
    z1 += __shfl_xor_sync(0xffffffff, z1, 1);
    z1 += __shfl_xor_sync(0xffffffff, z1, 2);

    __syncthreads();   // main-loop smem dead; safe to reuse
    float* Osm = (float*)smem;                        // [128][68] f32 (34.8 KB)
    float* Zs  = (float*)(smem + 128 * 68 * 4);       // [2][128]
    if (tg == 0) { Zs[wn * 128 + r0] = z0; Zs[wn * 128 + r0 + 8] = z1; }
    if (wn == 1) {
        #pragma unroll
        for (int jo = 0; jo < 8; jo++) {
            int col = jo * 8 + 2 * tg;
            *(float2*)&Osm[ r0      * 68 + col] = make_float2(oacc[jo][0], oacc[jo][1]);
            *(float2*)&Osm[(r0 + 8) * 68 + col] = make_float2(oacc[jo][2], oacc[jo][3]);
        }
    }
    __syncthreads();
    if (wn == 0) {
        float zr0 = 1.f / (Zs[r0]     + Zs[128 + r0]);
        float zr1 = 1.f / (Zs[r0 + 8] + Zs[128 + r0 + 8]);
        float* Pd = &g_parts[h][m0][0];
        #pragma unroll
        for (int jo = 0; jo < 8; jo++) {
            int col = jo * 8 + 2 * tg;
            float2 a0 = *(float2*)&Osm[ r0      * 68 + col];
            float2 a1 = *(float2*)&Osm[(r0 + 8) * 68 + col];
            *(float2*)&Pd[ r0      * DHEAD + col] =
                make_float2((oacc[jo][0] + a0.x) * zr0, (oacc[jo][1] + a0.y) * zr0);
            *(float2*)&Pd[(r0 + 8) * DHEAD + col] =
                make_float2((oacc[jo][2] + a1.x) * zr1, (oacc[jo][3] + a1.y) * zr1);
        }
    }
}

// ---------------------------------------------------------------------------
// Combine (proven): out = (1/8) * sum_h parts, float2 granularity
// ---------------------------------------------------------------------------
__global__ void combine_kernel(float* __restrict__ out) {
    int i = blockIdx.x * blockDim.x + threadIdx.x;   // float2 idx: 131072
    float2 s = make_float2(0.f, 0.f);
    #pragma unroll
    for (int h = 0; h < HEADS; h++) {
        float2 a = ((const float2*)&g_parts[h][0][0])[i];
        s.x += a.x; s.y += a.y;
    }
    ((float2*)out)[i] = make_float2(s.x * 0.125f, s.y * 0.125f);
}

extern "C" void kernel_launch(void* const* d_in, const int* in_sizes, int n_in,
                              void* d_out, int out_size) {
    const float* X  = (const float*)d_in[0];
    const float* Wq = (const float*)d_in[1];
    const float* bq = (const float*)d_in[2];
    const float* Wk = (const float*)d_in[3];
    const float* bk = (const float*)d_in[4];
    const float* Wv = (const float*)d_in[5];
    const float* bv = (const float*)d_in[6];
    float* out = (float*)d_out;

    cudaFuncSetAttribute(proj_kernel, cudaFuncAttributeMaxDynamicSharedMemorySize, PROJ_SMEM);
    cudaFuncSetAttribute(attn_kernel, cudaFuncAttributeMaxDynamicSharedMemorySize, ATTN_SMEM);

    convert_kernel<<<(262144 + 3 * 32768) / 256, 256>>>(X, Wq, Wk, Wv);

    dim3 pg(N_TOK / 128, 1536 / 128);
    proj_kernel<<<pg, 512, PROJ_SMEM>>>(bq, bk, bv);

    dim3 ag(N_TOK / 128, HEADS);
    attn_kernel<<<ag, 512, ATTN_SMEM>>>();

    combine_kernel<<<(N_TOK * DHEAD / 2) / 256, 256>>>(out);
}

// round 17
// speedup vs baseline: 1.0438x; 1.0438x over previous
#include <cuda_runtime.h>
#include <cuda_fp16.h>
#include <cstdint>

#define N_TOK 4096
#define INCH  256
#define HEADS 8
#define DHEAD 64
#define PROJ  512

// Scratch (allocation-free rule: __device__ globals)
__device__ __half g_xh[N_TOK][INCH];             // X fp16 (2 MB)
__device__ __half g_wh[3][PROJ][INCH];           // Wq/Wk/Wv fp16 (0.75 MB)
__device__ __half g_qh[HEADS][N_TOK][DHEAD];     // Q fp16 (4 MB)
__device__ __half g_kh[HEADS][N_TOK][DHEAD];     // K fp16 (4 MB)
__device__ __half g_vh[HEADS][N_TOK][DHEAD];     // V fp16 (4 MB)
__device__ float  g_parts[HEADS][N_TOK][DHEAD];  // per-head normalized O (8 MB)

__device__ __forceinline__ uint32_t pack_f16(float lo, float hi) {
    uint32_t r;
    asm("cvt.rn.f16x2.f32 %0, %1, %2;" : "=r"(r) : "f"(hi), "f"(lo));
    return r;
}

__device__ __forceinline__ void mma_f16(float c[4], const uint32_t a[4], uint32_t b0, uint32_t b1) {
    asm volatile(
        "mma.sync.aligned.m16n8k16.row.col.f32.f16.f16.f32 "
        "{%0,%1,%2,%3}, {%4,%5,%6,%7}, {%8,%9}, {%0,%1,%2,%3};"
        : "+f"(c[0]), "+f"(c[1]), "+f"(c[2]), "+f"(c[3])
        : "r"(a[0]), "r"(a[1]), "r"(a[2]), "r"(a[3]), "r"(b0), "r"(b1));
}

__device__ __forceinline__ uint32_t smem_u32(const void* p) {
    uint32_t a;
    asm("{ .reg .u64 t; cvta.to.shared.u64 t, %1; cvt.u32.u64 %0, t; }" : "=r"(a) : "l"(p));
    return a;
}

__device__ __forceinline__ void cpasync16(uint32_t dst, const void* src) {
    asm volatile("cp.async.cg.shared.global [%0], [%1], 16;" :: "r"(dst), "l"(src) : "memory");
}

// sigmoid on an f16x2 pair of raw logits: p = 0.5*tanh(0.5*x) + 0.5
__device__ __forceinline__ uint32_t sigmoid_f16x2(float s0, float s1) {
    uint32_t hx = pack_f16(s0 * 0.5f, s1 * 0.5f);
    uint32_t t, p;
    asm("tanh.approx.f16x2 %0, %1;" : "=r"(t) : "r"(hx));
    asm("fma.rn.f16x2 %0, %1, %2, %2;" : "=r"(p) : "r"(t), "r"(0x38003800u));
    return p;
}

// ---------------------------------------------------------------------------
// Convert: X, Wq, Wk, Wv f32 -> fp16 scratch. 360448 float4 total.
// ---------------------------------------------------------------------------
__global__ void convert_kernel(const float* __restrict__ X,
                               const float* __restrict__ Wq,
                               const float* __restrict__ Wk,
                               const float* __restrict__ Wv) {
    int i = blockIdx.x * blockDim.x + threadIdx.x;   // float4 index
    const float* src;
    __half* dst;
    int off;
    if (i < 262144) {                // X: 4096*256/4
        src = X; dst = &g_xh[0][0]; off = i;
    } else {
        int j = i - 262144;          // W: 3 * 32768
        int w = j >> 15; off = j & 32767;
        src = (w == 0) ? Wq : (w == 1) ? Wk : Wv;
        dst = &g_wh[w][0][0];
    }
    float4 v = ((const float4*)src)[off];
    uint2 o;
    o.x = pack_f16(v.x, v.y);
    o.y = pack_f16(v.z, v.w);
    ((uint2*)dst)[off] = o;
}

// ---------------------------------------------------------------------------
// Projection (R12-proven): fused fp16 GEMM C[4096][1536] = Xh @ Wh^T + b.
// CTA 64(m) x 64(p), K-chunks of 64, warps 4(m) x 2(p), cp.async double buffer.
// ---------------------------------------------------------------------------
#define PJ_STG 9216u
#define PROJ_SMEM (4 * PJ_STG)

__global__ __launch_bounds__(256) void proj_kernel(
        const float* __restrict__ bq, const float* __restrict__ bk,
        const float* __restrict__ bv) {
    extern __shared__ char smem[];
    const uint32_t sbase = smem_u32(smem);
    const uint32_t sX = sbase;
    const uint32_t sW = sbase + 2 * PJ_STG;

    const int m0  = blockIdx.x * 64;
    const int p0g = blockIdx.y * 64;
    const int which = p0g >> 9;
    const int p0i = p0g & 511;
    const float* bias = (which == 0) ? bq : (which == 1) ? bk : bv;
    __half* dst = (which == 0) ? &g_qh[0][0][0] : (which == 1) ? &g_kh[0][0][0]
                                                               : &g_vh[0][0][0];

    const int tid = threadIdx.x;
    const int lane = tid & 31, warp = tid >> 5;
    const int wm = warp & 3, wn = warp >> 2;
    const int g = lane >> 2, tg = lane & 3;

    const int a_row = lane & 15;
    const int a_col = (lane >> 4) * 8;
    const int kb_row = (lane & 7) + ((lane >> 4) & 1) * 8;
    const int kb_col = ((lane >> 3) & 1) * 8;

    const __half* Xg = &g_xh[m0][0];
    const __half* Wg = &g_wh[which][p0i][0];

    float acc[4][4] = {};

    {
        #pragma unroll
        for (int j = 0; j < 2; j++) {
            int e = tid + j * 256;
            int l = e >> 3, c = e & 7;
            cpasync16(sX + (uint32_t)(l * 144 + c * 16), Xg + l * INCH + c * 8);
            cpasync16(sW + (uint32_t)(l * 144 + c * 16), Wg + l * INCH + c * 8);
        }
        asm volatile("cp.async.commit_group;" ::: "memory");
    }

    #pragma unroll
    for (int kc = 0; kc < INCH / 64; kc++) {
        const int stg = kc & 1;
        asm volatile("cp.async.wait_group 0;" ::: "memory");
        __syncthreads();

        if (kc + 1 < INCH / 64) {
            const int k0n = (kc + 1) * 64;
            const uint32_t xd = sX + (uint32_t)(1 - stg) * PJ_STG;
            const uint32_t wd = sW + (uint32_t)(1 - stg) * PJ_STG;
            #pragma unroll
            for (int j = 0; j < 2; j++) {
                int e = tid + j * 256;
                int l = e >> 3, c = e & 7;
                cpasync16(xd + (uint32_t)(l * 144 + c * 16), Xg + l * INCH + k0n + c * 8);
                cpasync16(wd + (uint32_t)(l * 144 + c * 16), Wg + l * INCH + k0n + c * 8);
            }
            asm volatile("cp.async.commit_group;" ::: "memory");
        }

        const uint32_t xb = sX + (uint32_t)stg * PJ_STG;
        const uint32_t wb = sW + (uint32_t)stg * PJ_STG;

        #pragma unroll
        for (int ks = 0; ks < 4; ks++) {
            uint32_t a[4];
            {
                uint32_t addr = xb + (uint32_t)((wm * 16 + a_row) * 144 + (ks * 16 + a_col) * 2);
                asm volatile(
                    "ldmatrix.sync.aligned.m8n8.x4.shared.b16 {%0,%1,%2,%3}, [%4];"
                    : "=r"(a[0]), "=r"(a[1]), "=r"(a[2]), "=r"(a[3]) : "r"(addr));
            }
            #pragma unroll
            for (int gi = 0; gi < 2; gi++) {
                uint32_t addr = wb + (uint32_t)((wn * 32 + gi * 16 + kb_row) * 144
                                                + (ks * 16 + kb_col) * 2);
                uint32_t b0_, b1_, b2_, b3_;
                asm volatile(
                    "ldmatrix.sync.aligned.m8n8.x4.shared.b16 {%0,%1,%2,%3}, [%4];"
                    : "=r"(b0_), "=r"(b1_), "=r"(b2_), "=r"(b3_) : "r"(addr));
                mma_f16(acc[gi*2],     a, b0_, b1_);
                mma_f16(acc[gi*2 + 1], a, b2_, b3_);
            }
        }
    }

    #pragma unroll
    for (int j = 0; j < 4; j++) {
        int inner = p0i + wn * 32 + j * 8 + 2 * tg;
        float b0 = bias[inner], b1 = bias[inner + 1];
        int hd = inner >> 6, d = inner & 63;
        int row0 = m0 + wm * 16 + g;
        *(uint32_t*)&dst[(hd * N_TOK + row0    ) * DHEAD + d] =
            pack_f16(acc[j][0] + b0, acc[j][1] + b1);
        *(uint32_t*)&dst[(hd * N_TOK + row0 + 8) * DHEAD + d] =
            pack_f16(acc[j][2] + b0, acc[j][3] + b1);
    }
}

// ---------------------------------------------------------------------------
// Attention v5: one (query-tile 128, head) per CTA; grid (32, 8), 512 threads,
// warps 8(m) x 2(n). Sigmoid in f16x2 (tanh.approx.f16x2) — half the MUFU.
// Z row-sums via an extra ones-column MMA (exact f32 accumulation of the same
// fp16 P used in the numerator; no shuffles, no scalar Z adds).
// cp.async double buffer; epilogue: in-CTA wn reduction + normalization.
// ---------------------------------------------------------------------------
#define KV_STG 9216u   // 64 rows * 72 f16 * 2B (144B rows: LDSM conflict-free)
#define ATTN_SMEM (4 * KV_STG)

__global__ __launch_bounds__(512, 1) void attn_kernel() {
    extern __shared__ char smem[];
    const uint32_t sbase = smem_u32(smem);
    const uint32_t sK = sbase;                 // K stages at 0, KV_STG
    const uint32_t sV = sbase + 2 * KV_STG;    // V stages follow

    const int m0 = blockIdx.x * 128;
    const int h  = blockIdx.y;
    const int tid = threadIdx.x;
    const int lane = tid & 31, warp = tid >> 5;
    const int wm = warp & 7, wn = warp >> 3;   // 8(m) x 2(n)
    const int g = lane >> 2, tg = lane & 3;
    const int r0 = wm * 16 + g;                // [0, 128)

    // Q fragments fp16: qa[kstep][0..3] for m16n8k16
    uint32_t qa[4][4];
    {
        const __half* Qg = &g_qh[h][m0][0];
        #pragma unroll
        for (int ks = 0; ks < 4; ks++) {
            qa[ks][0] = *(const uint32_t*)&Qg[ r0      * DHEAD + ks*16 + 2*tg    ];
            qa[ks][1] = *(const uint32_t*)&Qg[(r0 + 8) * DHEAD + ks*16 + 2*tg    ];
            qa[ks][2] = *(const uint32_t*)&Qg[ r0      * DHEAD + ks*16 + 2*tg + 8];
            qa[ks][3] = *(const uint32_t*)&Qg[(r0 + 8) * DHEAD + ks*16 + 2*tg + 8];
        }
    }

    const __half* Kg = &g_kh[h][0][0];
    const __half* Vg = &g_vh[h][0][0];

    // ldmatrix lane roles
    const int lm_row = (lane & 7) + ((lane >> 3) & 1) * 8;   // V: k row within 16
    const int lm_col = ((lane >> 4) & 1) * 8;                // V: n col within 16
    const int kb_row = (lane & 7) + ((lane >> 4) & 1) * 8;   // K: n row within 16
    const int kb_col = ((lane >> 3) & 1) * 8;                // K: k half

    float oacc[8][4] = {};
    float zmma[4] = {};   // Z row-sums via ones-MMA (cols all equal)

    // prefetch tile 0: 512 threads cover 64 rows x 8 chunks of K and V
    {
        int l = tid >> 3, c = tid & 7;
        cpasync16(sK + (uint32_t)(l * 144 + c * 16), Kg + l * 64 + c * 8);
        cpasync16(sV + (uint32_t)(l * 144 + c * 16), Vg + l * 64 + c * 8);
        asm volatile("cp.async.commit_group;" ::: "memory");
    }

    for (int t = 0; t < N_TOK / 64; ++t) {
        const int stg = t & 1;
        asm volatile("cp.async.wait_group 0;" ::: "memory");
        __syncthreads();

        // prefetch t+1 into other stage
        if (t + 1 < N_TOK / 64) {
            const __half* Kn = Kg + (t + 1) * 64 * DHEAD;
            const __half* Vn = Vg + (t + 1) * 64 * DHEAD;
            const uint32_t kd = sK + (uint32_t)(1 - stg) * KV_STG;
            const uint32_t vd = sV + (uint32_t)(1 - stg) * KV_STG;
            int l = tid >> 3, c = tid & 7;
            cpasync16(kd + (uint32_t)(l * 144 + c * 16), Kn + l * 64 + c * 8);
            cpasync16(vd + (uint32_t)(l * 144 + c * 16), Vn + l * 64 + c * 8);
            asm volatile("cp.async.commit_group;" ::: "memory");
        }

        const uint32_t kb = sK + (uint32_t)stg * KV_STG;
        const uint32_t vb = sV + (uint32_t)stg * KV_STG;

        // ---- S = Q @ K^T (fp16 MMA), warp cols [wn*32, +32)
        float sacc[4][4] = {};
        #pragma unroll
        for (int ks = 0; ks < 4; ks++) {
            #pragma unroll
            for (int gi = 0; gi < 2; gi++) {
                uint32_t addr = kb
                    + (uint32_t)((wn * 32 + gi * 16 + kb_row) * 144)
                    + (uint32_t)((ks * 16 + kb_col) * 2);
                uint32_t b0_, b1_, b2_, b3_;
                asm volatile(
                    "ldmatrix.sync.aligned.m8n8.x4.shared.b16 {%0,%1,%2,%3}, [%4];"
                    : "=r"(b0_), "=r"(b1_), "=r"(b2_), "=r"(b3_) : "r"(addr));
                mma_f16(sacc[gi*2],     qa[ks], b0_, b1_);
                mma_f16(sacc[gi*2 + 1], qa[ks], b2_, b3_);
            }
        }

        // ---- sigmoid -> P (fp16 A-fragments in regs), f16x2 tanh path
        uint32_t pf[2][4];
        #pragma unroll
        for (int j = 0; j < 4; j++) {
            pf[j >> 1][(j & 1) * 2 + 0] = sigmoid_f16x2(sacc[j][0], sacc[j][1]);
            pf[j >> 1][(j & 1) * 2 + 1] = sigmoid_f16x2(sacc[j][2], sacc[j][3]);
        }

        // ---- Z += P @ ones (exact row-sum of fp16 P, f32 accum; no LDSM)
        #pragma unroll
        for (int kc = 0; kc < 2; kc++)
            mma_f16(zmma, pf[kc], 0x3C003C00u, 0x3C003C00u);

        // ---- O += P @ V (fp16 MMA), warp's l-slice = [wn*32 + kc*16, +16)
        #pragma unroll
        for (int kc = 0; kc < 2; kc++) {
            const uint32_t rowb = vb + (uint32_t)((wn * 32 + kc * 16 + lm_row) * 144);
            #pragma unroll
            for (int jp = 0; jp < 4; jp++) {
                uint32_t r0_, r1_, r2_, r3_;
                uint32_t addr = rowb + (uint32_t)((jp * 16 + lm_col) * 2);
                asm volatile(
                    "ldmatrix.sync.aligned.m8n8.x4.trans.shared.b16 {%0,%1,%2,%3}, [%4];"
                    : "=r"(r0_), "=r"(r1_), "=r"(r2_), "=r"(r3_) : "r"(addr));
                mma_f16(oacc[2*jp],     pf[kc], r0_, r1_);
                mma_f16(oacc[2*jp + 1], pf[kc], r2_, r3_);
            }
        }
    }

    // ================= epilogue: in-CTA reduction + normalize =================
    // zmma[0] = Z(row r0), zmma[2] = Z(row r0+8) over this warp's 32-key slices
    // (all n-cols identical; every lane holds the full row sum — no shuffles)
    __syncthreads();   // main-loop smem dead; safe to reuse
    float* Osm = (float*)smem;                        // [128][68] f32 (34.8 KB)
    float* Zs  = (float*)(smem + 128 * 68 * 4);       // [2][128]
    if (tg == 0) { Zs[wn * 128 + r0] = zmma[0]; Zs[wn * 128 + r0 + 8] = zmma[2]; }
    if (wn == 1) {
        #pragma unroll
        for (int jo = 0; jo < 8; jo++) {
            int col = jo * 8 + 2 * tg;
            *(float2*)&Osm[ r0      * 68 + col] = make_float2(oacc[jo][0], oacc[jo][1]);
            *(float2*)&Osm[(r0 + 8) * 68 + col] = make_float2(oacc[jo][2], oacc[jo][3]);
        }
    }
    __syncthreads();
    if (wn == 0) {
        float zr0 = 1.f / (Zs[r0]     + Zs[128 + r0]);
        float zr1 = 1.f / (Zs[r0 + 8] + Zs[128 + r0 + 8]);
        float* Pd = &g_parts[h][m0][0];
        #pragma unroll
        for (int jo = 0; jo < 8; jo++) {
            int col = jo * 8 + 2 * tg;
            float2 a0 = *(float2*)&Osm[ r0      * 68 + col];
            float2 a1 = *(float2*)&Osm[(r0 + 8) * 68 + col];
            *(float2*)&Pd[ r0      * DHEAD + col] =
                make_float2((oacc[jo][0] + a0.x) * zr0, (oacc[jo][1] + a0.y) * zr0);
            *(float2*)&Pd[(r0 + 8) * DHEAD + col] =
                make_float2((oacc[jo][2] + a1.x) * zr1, (oacc[jo][3] + a1.y) * zr1);
        }
    }
}

// ---------------------------------------------------------------------------
// Combine (proven): out = (1/8) * sum_h parts, float2 granularity
// ---------------------------------------------------------------------------
__global__ void combine_kernel(float* __restrict__ out) {
    int i = blockIdx.x * blockDim.x + threadIdx.x;   // float2 idx: 131072
    float2 s = make_float2(0.f, 0.f);
    #pragma unroll
    for (int h = 0; h < HEADS; h++) {
        float2 a = ((const float2*)&g_parts[h][0][0])[i];
        s.x += a.x; s.y += a.y;
    }
    ((float2*)out)[i] = make_float2(s.x * 0.125f, s.y * 0.125f);
}

extern "C" void kernel_launch(void* const* d_in, const int* in_sizes, int n_in,
                              void* d_out, int out_size) {
    const float* X  = (const float*)d_in[0];
    const float* Wq = (const float*)d_in[1];
    const float* bq = (const float*)d_in[2];
    const float* Wk = (const float*)d_in[3];
    const float* bk = (const float*)d_in[4];
    const float* Wv = (const float*)d_in[5];
    const float* bv = (const float*)d_in[6];
    float* out = (float*)d_out;

    cudaFuncSetAttribute(proj_kernel, cudaFuncAttributeMaxDynamicSharedMemorySize, PROJ_SMEM);
    cudaFuncSetAttribute(attn_kernel, cudaFuncAttributeMaxDynamicSharedMemorySize, ATTN_SMEM);

    convert_kernel<<<(262144 + 3 * 32768) / 256, 256>>>(X, Wq, Wk, Wv);

    dim3 pg(N_TOK / 64, 1536 / 64);
    proj_kernel<<<pg, 256, PROJ_SMEM>>>(bq, bk, bv);

    dim3 ag(N_TOK / 128, HEADS);
    attn_kernel<<<ag, 512, ATTN_SMEM>>>();

    combine_kernel<<<(N_TOK * DHEAD / 2) / 256, 256>>>(out);
}